// round 5
// baseline (speedup 1.0000x reference)
#include <cuda_runtime.h>
#include <cstdint>

// NLinear via mma.sync tf32 (base sm_100 target).
// R5: convert-to-tf32 ONCE in a smem repack pass; hot loop = wide LDS + HMMA only.
// out[b,n,o] = sum_i x[b,n,i]*W[n,i,o] + bias[n,o]
// x[256,128,512] f32, W[128,512,512] f32, bias[128,512] f32, out[256,128,512] f32

static constexpr int N_POS = 128;
static constexpr int D_IN  = 512;
static constexpr int D_OUT = 512;
static constexpr int BATCH = 256;
static constexpr int XSTR  = N_POS * D_IN;   // 65536
static constexpr int WSTR  = D_IN * D_OUT;   // 262144

static constexpr int BM = 128;
static constexpr int BN = 128;
static constexpr int BK = 32;
static constexpr int KITERS = D_IN / BK;     // 16

// Raw staging (cp.async target), padded for conflict-free repack gathers.
static constexpr int RA_STR = 36;            // A raw row stride (floats); bank = 4g+t
static constexpr int RB_STR = 136;           // B raw row stride (floats); bank = 8t+g
static constexpr int RAW_A_ELE = BM * RA_STR;        // 4608
static constexpr int RAW_B_ELE = BK * RB_STR;        // 4352
static constexpr int RAW_ELE   = RAW_A_ELE + RAW_B_ELE;  // 8960

// Packed fragment region (tf32 bits, mma register layout), double buffered.
// A: 8 r16-blocks x 4 ks x 32 lanes x 4 regs = 4096
// B: 16 n8-blocks x 4 ks x 32 lanes x 2 regs = 4096
static constexpr int PK_A_ELE  = 4096;
static constexpr int PK_ELE    = 8192;               // A + B per stage
static constexpr int SMEM_ELE  = RAW_ELE + 2 * PK_ELE;   // 25344
static constexpr int SMEM_BYTES = SMEM_ELE * 4;          // 101376

__device__ __forceinline__ void cp16(float* dst_smem, const float* src) {
    uint32_t d = (uint32_t)__cvta_generic_to_shared(dst_smem);
    asm volatile("cp.async.cg.shared.global [%0], [%1], 16;" :: "r"(d), "l"(src));
}
__device__ __forceinline__ void cp_commit() {
    asm volatile("cp.async.commit_group;" ::: "memory");
}
template <int N>
__device__ __forceinline__ void cp_wait() {
    asm volatile("cp.async.wait_group %0;" :: "n"(N) : "memory");
}
__device__ __forceinline__ uint32_t f2tf32(float f) {
    uint32_t r;
    asm("cvt.rna.tf32.f32 %0, %1;" : "=r"(r) : "f"(f));
    return r;
}
__device__ __forceinline__ void mma_tf32(float c[4],
                                         const uint32_t a[4],
                                         const uint32_t b[2]) {
    asm volatile(
        "mma.sync.aligned.m16n8k8.row.col.f32.tf32.tf32.f32 "
        "{%0,%1,%2,%3}, {%4,%5,%6,%7}, {%8,%9}, {%0,%1,%2,%3};"
        : "+f"(c[0]), "+f"(c[1]), "+f"(c[2]), "+f"(c[3])
        : "r"(a[0]), "r"(a[1]), "r"(a[2]), "r"(a[3]), "r"(b[0]), "r"(b[1]));
}

__device__ __forceinline__ void prefetch_raw(float* sm, const float* xb,
                                             const float* wb, int k0, int tid)
{
    float* A = sm;
    float* B = sm + RAW_A_ELE;
    #pragma unroll
    for (int j = 0; j < 4; j++) {            // A: 128 x 32 = 1024 x 16B
        int c  = tid + j * 256;
        int m  = c >> 3;
        int kc = c & 7;
        cp16(A + m * RA_STR + kc * 4, xb + (size_t)m * XSTR + k0 + kc * 4);
    }
    #pragma unroll
    for (int j = 0; j < 4; j++) {            // B: 32 x 128 = 1024 x 16B
        int c  = tid + j * 256;
        int kr = c >> 5;
        int nc = c & 31;
        cp16(B + kr * RB_STR + nc * 4, wb + (size_t)(k0 + kr) * D_OUT + nc * 4);
    }
    cp_commit();
}

__global__ __launch_bounds__(256, 2)
void nlinear_mma_kernel(const float* __restrict__ x,
                        const float* __restrict__ w,
                        const float* __restrict__ bias,
                        float* __restrict__ out)
{
    extern __shared__ float sm[];

    const int tid = threadIdx.x;
    const int wid = tid >> 5;
    const int lid = tid & 31;
    const int g   = lid >> 2;   // 0..7
    const int t   = lid & 3;    // 0..3

    const int n     = blockIdx.z;
    const int obase = blockIdx.x * BN;
    const int mbase = blockIdx.y * BM;

    // warp grid 2 (M) x 4 (N): warp tile 64 x 32
    const int wm0 = (wid & 1) * 64;
    const int wn0 = (wid >> 1) * 32;
    const int ar16 = wm0 >> 4;   // 0 or 4: base r16 block
    const int bn8  = wn0 >> 3;   // 0,4,8,12: base n8 block

    const float* xb = x + (size_t)mbase * XSTR + (size_t)n * D_IN;
    const float* wb = w + (size_t)n * WSTR + obase;

    float* rawA = sm;
    float* rawB = sm + RAW_A_ELE;

    float acc[4][4][4];
    #pragma unroll
    for (int mt = 0; mt < 4; mt++)
        #pragma unroll
        for (int nt = 0; nt < 4; nt++)
            #pragma unroll
            for (int q = 0; q < 4; q++)
                acc[mt][nt][q] = 0.0f;

    prefetch_raw(sm, xb, wb, 0, tid);

    for (int it = 0; it < KITERS; ++it) {
        cp_wait<0>();
        __syncthreads();                      // raw tile `it` visible to all

        float* pk  = sm + RAW_ELE + (it & 1) * PK_ELE;
        float* pkb = pk + PK_A_ELE;

        // ---- Repack A: tf32-convert into fragment layout ----
        // slot (r16, ks, lane): 4 regs {(g,t),(g+8,t),(g,t+4),(g+8,t+4)}
        #pragma unroll
        for (int r = 0; r < 4; r++) {
            const int p   = r * 8 + wid;      // 0..31 -> (r16 = p>>2, ks = p&3)
            const int r16 = p >> 2;
            const int ks  = p & 3;
            const float* src = rawA + (r16 * 16 + g) * RA_STR + ks * 8 + t;
            uint4 u;
            u.x = f2tf32(src[0]);
            u.y = f2tf32(src[8 * RA_STR]);
            u.z = f2tf32(src[4]);
            u.w = f2tf32(src[8 * RA_STR + 4]);
            *(uint4*)(pk + p * 128 + lid * 4) = u;
        }
        // ---- Repack B ----
        // slot (n8, ks, lane): 2 regs {(t, g),(t+4, g)} (k-row, n-col)
        #pragma unroll
        for (int r = 0; r < 8; r++) {
            const int p  = r * 8 + wid;       // 0..63 -> (n8 = p>>2, ks = p&3)
            const int n8 = p >> 2;
            const int ks = p & 3;
            const float* src = rawB + (ks * 8 + t) * RB_STR + n8 * 8 + g;
            uint2 u;
            u.x = f2tf32(src[0]);
            u.y = f2tf32(src[4 * RB_STR]);
            *(uint2*)(pkb + p * 64 + lid * 2) = u;
        }
        __syncthreads();                      // packed ready; raw buffer free

        if (it + 1 < KITERS)
            prefetch_raw(sm, xb, wb, (it + 1) * BK, tid);  // overlaps compute

        // ---- Hot loop: wide LDS + HMMA only ----
        #pragma unroll
        for (int ks = 0; ks < 4; ks++) {
            uint32_t a[4][4];
            uint32_t b[4][2];
            #pragma unroll
            for (int mt = 0; mt < 4; mt++)
                *(uint4*)a[mt] = *(const uint4*)(pk + (ar16 + mt) * 512 + ks * 128 + lid * 4);
            #pragma unroll
            for (int nt = 0; nt < 4; nt++)
                *(uint2*)b[nt] = *(const uint2*)(pkb + (bn8 + nt) * 256 + ks * 64 + lid * 2);
            #pragma unroll
            for (int mt = 0; mt < 4; mt++)
                #pragma unroll
                for (int nt = 0; nt < 4; nt++)
                    mma_tf32(acc[mt][nt], a[mt], b[nt]);
        }
    }

    // ---- Epilogue: bias + store ----
    const float* brow = bias + (size_t)n * D_OUT + obase;
    #pragma unroll
    for (int mt = 0; mt < 4; mt++) {
        const int r0 = mbase + wm0 + 16 * mt + g;
        float* o0 = out + (size_t)r0 * XSTR + (size_t)n * D_OUT + obase;
        float* o1 = o0 + (size_t)8 * XSTR;
        #pragma unroll
        for (int nt = 0; nt < 4; nt++) {
            const int col = wn0 + 8 * nt + 2 * t;
            float2 bv = *(const float2*)(brow + col);
            float2 v0, v1;
            v0.x = acc[mt][nt][0] + bv.x;
            v0.y = acc[mt][nt][1] + bv.y;
            v1.x = acc[mt][nt][2] + bv.x;
            v1.y = acc[mt][nt][3] + bv.y;
            *(float2*)(o0 + col) = v0;
            *(float2*)(o1 + col) = v1;
        }
    }
}

extern "C" void kernel_launch(void* const* d_in, const int* in_sizes, int n_in,
                              void* d_out, int out_size)
{
    const float* x    = (const float*)d_in[0];
    const float* w    = (const float*)d_in[1];
    const float* bias = (const float*)d_in[2];
    float* out        = (float*)d_out;

    cudaFuncSetAttribute(nlinear_mma_kernel,
                         cudaFuncAttributeMaxDynamicSharedMemorySize, SMEM_BYTES);

    dim3 grid(D_OUT / BN, BATCH / BM, N_POS);   // (4, 2, 128)
    dim3 block(256);
    nlinear_mma_kernel<<<grid, block, SMEM_BYTES>>>(x, w, bias, out);
}